// round 5
// baseline (speedup 1.0000x reference)
#include <cuda_runtime.h>

#define NN 200000
#define NE 6400000
#define FIN 128
#define HID 16
#define SCAN_BLK 1024
#define NB_SCAN ((NN + SCAN_BLK - 1) / SCAN_BLK)   // 196

// ---- scratch (device globals; no allocation allowed) ----
__device__ __align__(16) float g_h[NN * HID];      // layer-1 transformed features
__device__ __align__(16) float g_h2[NN * HID];     // layer-2 transformed features
__device__ int   g_cnt[NN];                        // in-degree per node
__device__ int   g_rowptr[NN];                     // exclusive prefix of cnt
__device__ int   g_cursor[NN];                     // mutable copy for placement
__device__ int   g_bsum[256];                      // scan block sums
__device__ unsigned long long g_edges[NE];         // packed (src:int, w:float) grouped by dst

// ---------------------------------------------------------------------------
__global__ void zero_cnt_kernel(int* __restrict__ cnt) {
    int i = blockIdx.x * blockDim.x + threadIdx.x;
    if (i < NN) cnt[i] = 0;
}

__global__ void hist_kernel(const int* __restrict__ dst, int* __restrict__ cnt) {
    int e = blockIdx.x * blockDim.x + threadIdx.x;
    if (e < NE) atomicAdd(&cnt[__ldg(dst + e)], 1);
}

// per-block exclusive scan (Hillis-Steele), emits block sums
__global__ void scan1_kernel(const int* __restrict__ cnt, int* __restrict__ rowptr,
                             int* __restrict__ bsum) {
    __shared__ int s[SCAN_BLK];
    int i = blockIdx.x * SCAN_BLK + threadIdx.x;
    int v = (i < NN) ? cnt[i] : 0;
    s[threadIdx.x] = v;
    __syncthreads();
#pragma unroll
    for (int off = 1; off < SCAN_BLK; off <<= 1) {
        int t = (threadIdx.x >= off) ? s[threadIdx.x - off] : 0;
        __syncthreads();
        s[threadIdx.x] += t;
        __syncthreads();
    }
    if (i < NN) rowptr[i] = s[threadIdx.x] - v;      // exclusive
    if (threadIdx.x == SCAN_BLK - 1) bsum[blockIdx.x] = s[SCAN_BLK - 1];
}

// single-block exclusive scan of the block sums
__global__ void scan2_kernel(int* __restrict__ bsum, int nb) {
    __shared__ int s[256];
    int v = (threadIdx.x < nb) ? bsum[threadIdx.x] : 0;
    s[threadIdx.x] = v;
    __syncthreads();
#pragma unroll
    for (int off = 1; off < 256; off <<= 1) {
        int t = (threadIdx.x >= off) ? s[threadIdx.x - off] : 0;
        __syncthreads();
        s[threadIdx.x] += t;
        __syncthreads();
    }
    if (threadIdx.x < nb) bsum[threadIdx.x] = s[threadIdx.x] - v;
}

__global__ void addoff_kernel(int* __restrict__ rowptr, const int* __restrict__ bsum,
                              int* __restrict__ cursor) {
    int i = blockIdx.x * blockDim.x + threadIdx.x;
    if (i < NN) {
        int r = rowptr[i] + bsum[i >> 10];
        rowptr[i] = r;
        cursor[i] = r;
    }
}

// place each edge's packed (src, w) into its dst segment
__global__ void edge_place_kernel(const int* __restrict__ src, const int* __restrict__ dst,
                                  const float* __restrict__ w, int* __restrict__ cursor,
                                  unsigned long long* __restrict__ edges) {
    int e = blockIdx.x * blockDim.x + threadIdx.x;
    if (e >= NE) return;
    int d = __ldg(dst + e);
    int pos = atomicAdd(&cursor[d], 1);
    unsigned long long pk = (unsigned long long)(unsigned)__ldg(src + e) |
                            ((unsigned long long)__float_as_uint(__ldg(w + e)) << 32);
    edges[pos] = pk;
}

// ---------------------------------------------------------------------------
// h1pre = x @ W1   (N x 128 @ 128 x 16), warp per node.
// ---------------------------------------------------------------------------
__global__ void gemm1_kernel(const float* __restrict__ x,
                             const float* __restrict__ W1,
                             float* __restrict__ out) {
    __shared__ __align__(16) float sWt[HID * FIN];
    for (int i = threadIdx.x; i < HID * FIN; i += blockDim.x) {
        int j = i / FIN, k = i % FIN;
        sWt[i] = W1[k * HID + j];
    }
    __syncthreads();

    int gwarp = (blockIdx.x * blockDim.x + threadIdx.x) >> 5;
    int lane  = threadIdx.x & 31;
    if (gwarp >= NN) return;

    float4 xv = ((const float4*)(x + (size_t)gwarp * FIN))[lane];

    float acc[HID];
    const float4* sWt4 = (const float4*)sWt;
#pragma unroll
    for (int j = 0; j < HID; j++) {
        float4 wv = sWt4[j * (FIN / 4) + lane];
        acc[j] = xv.x * wv.x + xv.y * wv.y + xv.z * wv.z + xv.w * wv.w;
    }
#pragma unroll
    for (int j = 0; j < HID; j++) {
#pragma unroll
        for (int off = 16; off; off >>= 1)
            acc[j] += __shfl_xor_sync(0xFFFFFFFFu, acc[j], off);
    }
    if (lane < HID) out[(size_t)gwarp * HID + lane] = acc[lane];
}

// ---------------------------------------------------------------------------
// Warp-level gather core with high MLP:
// 1) one coalesced LDG.64 loads 32 edge records (lane i = record i),
// 2) each slot-lane shuffles its 4 records from registers,
// 3) issues its 4 independent random h[src] gathers back-to-back.
// Returns the float4 accumulator for chunk j (caller reduces across slots).
// ---------------------------------------------------------------------------
__device__ __forceinline__ float4 gather_accum(const unsigned long long* __restrict__ edges,
                                               const float* __restrict__ h,
                                               int start, int deg,
                                               int lane, int j, int slot) {
    float4 acc = make_float4(0.f, 0.f, 0.f, 0.f);
    for (int base = 0; base < deg; base += 32) {
        int idx = base + lane;
        unsigned long long pk = (idx < deg) ? __ldg(edges + start + idx) : 0ull;

        // distribute: slot s handles chunk-local edges s, s+8, s+16, s+24
        unsigned long long p0 = __shfl_sync(0xFFFFFFFFu, pk, slot);
        unsigned long long p1 = __shfl_sync(0xFFFFFFFFu, pk, slot + 8);
        unsigned long long p2 = __shfl_sync(0xFFFFFFFFu, pk, slot + 16);
        unsigned long long p3 = __shfl_sync(0xFFFFFFFFu, pk, slot + 24);

        bool v0 = (base + slot)      < deg;
        bool v1 = (base + slot + 8)  < deg;
        bool v2 = (base + slot + 16) < deg;
        bool v3 = (base + slot + 24) < deg;

        // 4 independent gathers in flight
        float4 g0, g1, g2, g3;
        if (v0) g0 = __ldg((const float4*)(h + (size_t)(unsigned)p0 * HID) + j);
        if (v1) g1 = __ldg((const float4*)(h + (size_t)(unsigned)p1 * HID) + j);
        if (v2) g2 = __ldg((const float4*)(h + (size_t)(unsigned)p2 * HID) + j);
        if (v3) g3 = __ldg((const float4*)(h + (size_t)(unsigned)p3 * HID) + j);

        if (v0) { float w = __uint_as_float((unsigned)(p0 >> 32));
                  acc.x += w * g0.x; acc.y += w * g0.y; acc.z += w * g0.z; acc.w += w * g0.w; }
        if (v1) { float w = __uint_as_float((unsigned)(p1 >> 32));
                  acc.x += w * g1.x; acc.y += w * g1.y; acc.z += w * g1.z; acc.w += w * g1.w; }
        if (v2) { float w = __uint_as_float((unsigned)(p2 >> 32));
                  acc.x += w * g2.x; acc.y += w * g2.y; acc.z += w * g2.z; acc.w += w * g2.w; }
        if (v3) { float w = __uint_as_float((unsigned)(p3 >> 32));
                  acc.x += w * g3.x; acc.y += w * g3.y; acc.z += w * g3.z; acc.w += w * g3.w; }
    }
    return acc;
}

// ---------------------------------------------------------------------------
// Gather pass 1: warp per node, no atomics.
// agg = sum_e w_e * h[src_e];  out = relu(agg + b1) @ W2  (fused epilogue).
// ---------------------------------------------------------------------------
__global__ void gather1_kernel(const unsigned long long* __restrict__ edges,
                               const int* __restrict__ rowptr,
                               const int* __restrict__ cnt,
                               const float* __restrict__ h,
                               const float* __restrict__ b1,
                               const float* __restrict__ W2,
                               float* __restrict__ out) {
    __shared__ __align__(16) float sW[HID * HID];
    __shared__ float sb[HID];
    __shared__ __align__(16) float sa[8][HID];     // 8 warps/block
    for (int i = threadIdx.x; i < HID * HID; i += blockDim.x) sW[i] = W2[i];
    if (threadIdx.x < HID) sb[threadIdx.x] = b1[threadIdx.x];
    __syncthreads();

    int n    = (blockIdx.x * blockDim.x + threadIdx.x) >> 5;   // exact: NN % 8 == 0
    int lane = threadIdx.x & 31;
    int wloc = threadIdx.x >> 5;
    int j    = lane & 3;
    int slot = lane >> 2;

    int start = __ldg(rowptr + n);
    int deg   = __ldg(cnt + n);

    float4 acc = gather_accum(edges, h, start, deg, lane, j, slot);

    // reduce across the 8 slots holding the same chunk j (lanes stride 4)
#pragma unroll
    for (int off = 4; off < 32; off <<= 1) {
        acc.x += __shfl_xor_sync(0xFFFFFFFFu, acc.x, off);
        acc.y += __shfl_xor_sync(0xFFFFFFFFu, acc.y, off);
        acc.z += __shfl_xor_sync(0xFFFFFFFFu, acc.z, off);
        acc.w += __shfl_xor_sync(0xFFFFFFFFu, acc.w, off);
    }
    if (lane < 4) *(float4*)&sa[wloc][4 * lane] = acc;   // lane == its chunk j
    __syncwarp();

    if (lane < HID) {
        float o = 0.f;
#pragma unroll
        for (int k = 0; k < HID; k++) {
            float a = fmaxf(sa[wloc][k] + sb[k], 0.f);
            o += a * sW[k * HID + lane];
        }
        out[(size_t)n * HID + lane] = o;
    }
}

// ---------------------------------------------------------------------------
// Gather pass 2: warp per node. agg2 = sum w*h2[src]; out = relu(agg2+b2)@Wd+bd.
// ---------------------------------------------------------------------------
__global__ void gather2_kernel(const unsigned long long* __restrict__ edges,
                               const int* __restrict__ rowptr,
                               const int* __restrict__ cnt,
                               const float* __restrict__ h,
                               const float* __restrict__ b2,
                               const float* __restrict__ Wd,
                               const float* __restrict__ bd,
                               float* __restrict__ out) {
    __shared__ float sb[HID], sw[HID];
    __shared__ float sbd;
    __shared__ __align__(16) float sa[8][HID];
    if (threadIdx.x < HID) { sb[threadIdx.x] = b2[threadIdx.x]; sw[threadIdx.x] = Wd[threadIdx.x]; }
    if (threadIdx.x == 0) sbd = bd[0];
    __syncthreads();

    int n    = (blockIdx.x * blockDim.x + threadIdx.x) >> 5;
    int lane = threadIdx.x & 31;
    int wloc = threadIdx.x >> 5;
    int j    = lane & 3;
    int slot = lane >> 2;

    int start = __ldg(rowptr + n);
    int deg   = __ldg(cnt + n);

    float4 acc = gather_accum(edges, h, start, deg, lane, j, slot);

#pragma unroll
    for (int off = 4; off < 32; off <<= 1) {
        acc.x += __shfl_xor_sync(0xFFFFFFFFu, acc.x, off);
        acc.y += __shfl_xor_sync(0xFFFFFFFFu, acc.y, off);
        acc.z += __shfl_xor_sync(0xFFFFFFFFu, acc.z, off);
        acc.w += __shfl_xor_sync(0xFFFFFFFFu, acc.w, off);
    }
    if (lane < 4) *(float4*)&sa[wloc][4 * lane] = acc;
    __syncwarp();

    if (lane == 0) {
        float o = sbd;
#pragma unroll
        for (int k = 0; k < HID; k++)
            o += fmaxf(sa[wloc][k] + sb[k], 0.f) * sw[k];
        out[n] = o;
    }
}

// ---------------------------------------------------------------------------
extern "C" void kernel_launch(void* const* d_in, const int* in_sizes, int n_in,
                              void* d_out, int out_size) {
    const float* x   = (const float*)d_in[0];
    const int*   src = (const int*)d_in[1];
    const int*   dst = (const int*)d_in[2];
    const float* ew  = (const float*)d_in[3];
    const float* W1  = (const float*)d_in[4];
    const float* b1  = (const float*)d_in[5];
    const float* W2  = (const float*)d_in[6];
    const float* b2  = (const float*)d_in[7];
    const float* Wd  = (const float*)d_in[8];
    const float* bd  = (const float*)d_in[9];
    float* out = (float*)d_out;

    float *hP, *h2P;
    int *cntP, *rowP, *curP, *bsP;
    unsigned long long *edgP;
    cudaGetSymbolAddress((void**)&hP,   g_h);
    cudaGetSymbolAddress((void**)&h2P,  g_h2);
    cudaGetSymbolAddress((void**)&cntP, g_cnt);
    cudaGetSymbolAddress((void**)&rowP, g_rowptr);
    cudaGetSymbolAddress((void**)&curP, g_cursor);
    cudaGetSymbolAddress((void**)&bsP,  g_bsum);
    cudaGetSymbolAddress((void**)&edgP, g_edges);

    const int TPB = 256;
    const int node_blocks  = (NN + TPB - 1) / TPB;
    const int edge_blocks  = (NE + TPB - 1) / TPB;
    const int gemm1_blocks = (NN * 32 + TPB - 1) / TPB;    // warp per node
    const int warp_blocks  = NN / (TPB / 32);              // 8 warps/block, exact

    // --- build CSR-by-dst (counting sort) ---
    zero_cnt_kernel<<<node_blocks, TPB>>>(cntP);
    hist_kernel<<<edge_blocks, TPB>>>(dst, cntP);
    scan1_kernel<<<NB_SCAN, SCAN_BLK>>>(cntP, rowP, bsP);
    scan2_kernel<<<1, 256>>>(bsP, NB_SCAN);
    addoff_kernel<<<node_blocks, TPB>>>(rowP, bsP, curP);
    edge_place_kernel<<<edge_blocks, TPB>>>(src, dst, ew, curP, edgP);

    // --- layer 1: transform, gather, fused relu/b1/@W2 -> g_h2 ---
    gemm1_kernel<<<gemm1_blocks, TPB>>>(x, W1, hP);
    gather1_kernel<<<warp_blocks, TPB>>>(edgP, rowP, cntP, hP, b1, W2, h2P);

    // --- layer 2: gather, fused relu/b2/@Wd+bd -> out ---
    gather2_kernel<<<warp_blocks, TPB>>>(edgP, rowP, cntP, h2P, b2, Wd, bd, out);
}

// round 6
// speedup vs baseline: 1.1362x; 1.1362x over previous
#include <cuda_runtime.h>

#define NN 200000
#define NE 6400000
#define FIN 128
#define HID 16
#define SCAN_BLK 1024
#define NB_SCAN ((NN + SCAN_BLK - 1) / SCAN_BLK)   // 196

// ---- scratch (device globals; no allocation allowed) ----
__device__ __align__(16) float g_h[NN * HID];      // layer-1 transformed features
__device__ __align__(16) float g_h2[NN * HID];     // layer-2 transformed features
__device__ int   g_cnt[NN];                        // in-degree per node
__device__ int   g_rowptr[NN];                     // exclusive prefix of cnt
__device__ int   g_cursor[NN];                     // mutable copy for placement
__device__ int   g_bsum[256];                      // scan block sums
__device__ unsigned long long g_edges[NE];         // packed (src:int, w:float) grouped by dst

// ---------------------------------------------------------------------------
__global__ void zero_cnt_kernel(int* __restrict__ cnt) {
    int i = blockIdx.x * blockDim.x + threadIdx.x;
    if (i < NN) cnt[i] = 0;
}

__global__ void hist_kernel(const int* __restrict__ dst, int* __restrict__ cnt) {
    int e = blockIdx.x * blockDim.x + threadIdx.x;
    if (e < NE) atomicAdd(&cnt[__ldcs(dst + e)], 1);
}

// per-block exclusive scan (Hillis-Steele), emits block sums
__global__ void scan1_kernel(const int* __restrict__ cnt, int* __restrict__ rowptr,
                             int* __restrict__ bsum) {
    __shared__ int s[SCAN_BLK];
    int i = blockIdx.x * SCAN_BLK + threadIdx.x;
    int v = (i < NN) ? cnt[i] : 0;
    s[threadIdx.x] = v;
    __syncthreads();
#pragma unroll
    for (int off = 1; off < SCAN_BLK; off <<= 1) {
        int t = (threadIdx.x >= off) ? s[threadIdx.x - off] : 0;
        __syncthreads();
        s[threadIdx.x] += t;
        __syncthreads();
    }
    if (i < NN) rowptr[i] = s[threadIdx.x] - v;      // exclusive
    if (threadIdx.x == SCAN_BLK - 1) bsum[blockIdx.x] = s[SCAN_BLK - 1];
}

// single-block exclusive scan of the block sums
__global__ void scan2_kernel(int* __restrict__ bsum, int nb) {
    __shared__ int s[256];
    int v = (threadIdx.x < nb) ? bsum[threadIdx.x] : 0;
    s[threadIdx.x] = v;
    __syncthreads();
#pragma unroll
    for (int off = 1; off < 256; off <<= 1) {
        int t = (threadIdx.x >= off) ? s[threadIdx.x - off] : 0;
        __syncthreads();
        s[threadIdx.x] += t;
        __syncthreads();
    }
    if (threadIdx.x < nb) bsum[threadIdx.x] = s[threadIdx.x] - v;
}

__global__ void addoff_kernel(int* __restrict__ rowptr, const int* __restrict__ bsum,
                              int* __restrict__ cursor) {
    int i = blockIdx.x * blockDim.x + threadIdx.x;
    if (i < NN) {
        int r = rowptr[i] + bsum[i >> 10];
        rowptr[i] = r;
        cursor[i] = r;
    }
}

// place each edge's packed (src, w) into its dst segment
__global__ void edge_place_kernel(const int* __restrict__ src, const int* __restrict__ dst,
                                  const float* __restrict__ w, int* __restrict__ cursor,
                                  unsigned long long* __restrict__ edges) {
    int e = blockIdx.x * blockDim.x + threadIdx.x;
    if (e >= NE) return;
    int d = __ldcs(dst + e);
    int pos = atomicAdd(&cursor[d], 1);
    unsigned long long pk = (unsigned long long)(unsigned)__ldcs(src + e) |
                            ((unsigned long long)__float_as_uint(__ldcs(w + e)) << 32);
    edges[pos] = pk;
}

// ---------------------------------------------------------------------------
// h1pre = x @ W1   (N x 128 @ 128 x 16), warp per node.
// ---------------------------------------------------------------------------
__global__ void gemm1_kernel(const float* __restrict__ x,
                             const float* __restrict__ W1,
                             float* __restrict__ out) {
    __shared__ __align__(16) float sWt[HID * FIN];
    for (int i = threadIdx.x; i < HID * FIN; i += blockDim.x) {
        int j = i / FIN, k = i % FIN;
        sWt[i] = W1[k * HID + j];
    }
    __syncthreads();

    int gwarp = (blockIdx.x * blockDim.x + threadIdx.x) >> 5;
    int lane  = threadIdx.x & 31;
    if (gwarp >= NN) return;

    float4 xv = __ldcs(((const float4*)(x + (size_t)gwarp * FIN)) + lane);

    float acc[HID];
    const float4* sWt4 = (const float4*)sWt;
#pragma unroll
    for (int j = 0; j < HID; j++) {
        float4 wv = sWt4[j * (FIN / 4) + lane];
        acc[j] = xv.x * wv.x + xv.y * wv.y + xv.z * wv.z + xv.w * wv.w;
    }
#pragma unroll
    for (int j = 0; j < HID; j++) {
#pragma unroll
        for (int off = 16; off; off >>= 1)
            acc[j] += __shfl_xor_sync(0xFFFFFFFFu, acc[j], off);
    }
    if (lane < HID) out[(size_t)gwarp * HID + lane] = acc[lane];
}

// ---------------------------------------------------------------------------
// Warp-level gather core, 8 slots x 4 chunk lanes, rotating edge prefetch.
// The next edge record is loaded BEFORE the current gather is consumed, so
// edge-load latency overlaps gather latency across iterations. __ldcs keeps
// the streaming edge array from evicting the L2-resident h table.
// ---------------------------------------------------------------------------
__device__ __forceinline__ float4 gather_accum(const unsigned long long* __restrict__ edges,
                                               const float* __restrict__ h,
                                               int start, int deg,
                                               int j, int slot) {
    float4 acc = make_float4(0.f, 0.f, 0.f, 0.f);
    int i = slot;
    if (i >= deg) return acc;
    unsigned long long pk = __ldcs(edges + start + i);
    while (true) {
        int inext = i + 8;
        bool more = inext < deg;
        unsigned long long pknext = 0ull;
        if (more) pknext = __ldcs(edges + start + inext);   // prefetch (independent)

        float we = __uint_as_float((unsigned)(pk >> 32));
        float4 v = __ldg((const float4*)(h + (size_t)(unsigned)pk * HID) + j);
        acc.x += we * v.x; acc.y += we * v.y; acc.z += we * v.z; acc.w += we * v.w;

        if (!more) break;
        pk = pknext;
        i = inext;
    }
    return acc;
}

// ---------------------------------------------------------------------------
// Gather pass 1: warp per node, no atomics.
// agg = sum_e w_e * h[src_e];  out = relu(agg + b1) @ W2  (fused epilogue).
// ---------------------------------------------------------------------------
__global__ void gather1_kernel(const unsigned long long* __restrict__ edges,
                               const int* __restrict__ rowptr,
                               const int* __restrict__ cnt,
                               const float* __restrict__ h,
                               const float* __restrict__ b1,
                               const float* __restrict__ W2,
                               float* __restrict__ out) {
    __shared__ __align__(16) float sW[HID * HID];
    __shared__ float sb[HID];
    __shared__ __align__(16) float sa[8][HID];     // 8 warps/block
    for (int i = threadIdx.x; i < HID * HID; i += blockDim.x) sW[i] = W2[i];
    if (threadIdx.x < HID) sb[threadIdx.x] = b1[threadIdx.x];
    __syncthreads();

    int n    = (blockIdx.x * blockDim.x + threadIdx.x) >> 5;   // exact: NN % 8 == 0
    int lane = threadIdx.x & 31;
    int wloc = threadIdx.x >> 5;
    int j    = lane & 3;
    int slot = lane >> 2;

    int start = __ldg(rowptr + n);
    int deg   = __ldg(cnt + n);

    float4 acc = gather_accum(edges, h, start, deg, j, slot);

    // reduce across the 8 slots holding the same chunk j (lanes stride 4)
#pragma unroll
    for (int off = 4; off < 32; off <<= 1) {
        acc.x += __shfl_xor_sync(0xFFFFFFFFu, acc.x, off);
        acc.y += __shfl_xor_sync(0xFFFFFFFFu, acc.y, off);
        acc.z += __shfl_xor_sync(0xFFFFFFFFu, acc.z, off);
        acc.w += __shfl_xor_sync(0xFFFFFFFFu, acc.w, off);
    }
    if (lane < 4) *(float4*)&sa[wloc][4 * lane] = acc;   // lane == its chunk j
    __syncwarp();

    if (lane < HID) {
        float o = 0.f;
#pragma unroll
        for (int k = 0; k < HID; k++) {
            float a = fmaxf(sa[wloc][k] + sb[k], 0.f);
            o += a * sW[k * HID + lane];
        }
        out[(size_t)n * HID + lane] = o;
    }
}

// ---------------------------------------------------------------------------
// Gather pass 2: warp per node. agg2 = sum w*h2[src]; out = relu(agg2+b2)@Wd+bd.
// ---------------------------------------------------------------------------
__global__ void gather2_kernel(const unsigned long long* __restrict__ edges,
                               const int* __restrict__ rowptr,
                               const int* __restrict__ cnt,
                               const float* __restrict__ h,
                               const float* __restrict__ b2,
                               const float* __restrict__ Wd,
                               const float* __restrict__ bd,
                               float* __restrict__ out) {
    __shared__ float sb[HID], sw[HID];
    __shared__ float sbd;
    __shared__ __align__(16) float sa[8][HID];
    if (threadIdx.x < HID) { sb[threadIdx.x] = b2[threadIdx.x]; sw[threadIdx.x] = Wd[threadIdx.x]; }
    if (threadIdx.x == 0) sbd = bd[0];
    __syncthreads();

    int n    = (blockIdx.x * blockDim.x + threadIdx.x) >> 5;
    int lane = threadIdx.x & 31;
    int wloc = threadIdx.x >> 5;
    int j    = lane & 3;
    int slot = lane >> 2;

    int start = __ldg(rowptr + n);
    int deg   = __ldg(cnt + n);

    float4 acc = gather_accum(edges, h, start, deg, j, slot);

#pragma unroll
    for (int off = 4; off < 32; off <<= 1) {
        acc.x += __shfl_xor_sync(0xFFFFFFFFu, acc.x, off);
        acc.y += __shfl_xor_sync(0xFFFFFFFFu, acc.y, off);
        acc.z += __shfl_xor_sync(0xFFFFFFFFu, acc.z, off);
        acc.w += __shfl_xor_sync(0xFFFFFFFFu, acc.w, off);
    }
    if (lane < 4) *(float4*)&sa[wloc][4 * lane] = acc;
    __syncwarp();

    if (lane == 0) {
        float o = sbd;
#pragma unroll
        for (int k = 0; k < HID; k++)
            o += fmaxf(sa[wloc][k] + sb[k], 0.f) * sw[k];
        out[n] = o;
    }
}

// ---------------------------------------------------------------------------
extern "C" void kernel_launch(void* const* d_in, const int* in_sizes, int n_in,
                              void* d_out, int out_size) {
    const float* x   = (const float*)d_in[0];
    const int*   src = (const int*)d_in[1];
    const int*   dst = (const int*)d_in[2];
    const float* ew  = (const float*)d_in[3];
    const float* W1  = (const float*)d_in[4];
    const float* b1  = (const float*)d_in[5];
    const float* W2  = (const float*)d_in[6];
    const float* b2  = (const float*)d_in[7];
    const float* Wd  = (const float*)d_in[8];
    const float* bd  = (const float*)d_in[9];
    float* out = (float*)d_out;

    float *hP, *h2P;
    int *cntP, *rowP, *curP, *bsP;
    unsigned long long *edgP;
    cudaGetSymbolAddress((void**)&hP,   g_h);
    cudaGetSymbolAddress((void**)&h2P,  g_h2);
    cudaGetSymbolAddress((void**)&cntP, g_cnt);
    cudaGetSymbolAddress((void**)&rowP, g_rowptr);
    cudaGetSymbolAddress((void**)&curP, g_cursor);
    cudaGetSymbolAddress((void**)&bsP,  g_bsum);
    cudaGetSymbolAddress((void**)&edgP, g_edges);

    const int TPB = 256;
    const int node_blocks  = (NN + TPB - 1) / TPB;
    const int edge_blocks  = (NE + TPB - 1) / TPB;
    const int gemm1_blocks = (NN * 32 + TPB - 1) / TPB;    // warp per node
    const int warp_blocks  = NN / (TPB / 32);              // 8 warps/block, exact

    // --- build CSR-by-dst (counting sort) ---
    zero_cnt_kernel<<<node_blocks, TPB>>>(cntP);
    hist_kernel<<<edge_blocks, TPB>>>(dst, cntP);
    scan1_kernel<<<NB_SCAN, SCAN_BLK>>>(cntP, rowP, bsP);
    scan2_kernel<<<1, 256>>>(bsP, NB_SCAN);
    addoff_kernel<<<node_blocks, TPB>>>(rowP, bsP, curP);
    edge_place_kernel<<<edge_blocks, TPB>>>(src, dst, ew, curP, edgP);

    // --- layer 1: transform, gather, fused relu/b1/@W2 -> g_h2 ---
    gemm1_kernel<<<gemm1_blocks, TPB>>>(x, W1, hP);
    gather1_kernel<<<warp_blocks, TPB>>>(edgP, rowP, cntP, hP, b1, W2, h2P);

    // --- layer 2: gather, fused relu/b2/@Wd+bd -> out ---
    gather2_kernel<<<warp_blocks, TPB>>>(edgP, rowP, cntP, h2P, b2, Wd, bd, out);
}